// round 2
// baseline (speedup 1.0000x reference)
#include <cuda_runtime.h>
#include <cstdint>

// Problem constants (static per reference: 8192x8192 input, 600 slices, 12500 out cols)
#define IN_COLS      8192
#define N_ROWS       8192
#define MAX_SLICES   1024
#define MAX_OUT_COLS 16384
#define TILE_COLS    256
#define ROWS_PER_BLK 8

// Scratch: output-column -> input-column map (no device allocs allowed).
__device__ int g_col_idx[MAX_OUT_COLS];

// One block: decode slices (int32 or int64), scan lengths, expand into g_col_idx.
__global__ void build_col_idx_kernel(const int* __restrict__ slices_raw, int n_slices) {
    __shared__ int s_scan[MAX_SLICES];
    __shared__ int s_is64;
    int t = threadIdx.x;

    if (t == 0) {
        // int64 little-endian: odd 32-bit words are high halves == 0.
        // int32: odd words are 'end' values >= 1. Check first few pairs.
        int z = 0;
        for (int k = 0; k < 4 && k < n_slices; k++)
            z |= slices_raw[4 * k + 1] | slices_raw[4 * k + 3];
        s_is64 = (z == 0) ? 1 : 0;
    }
    __syncthreads();
    int is64 = s_is64;

    int st = 0, len = 0;
    if (t < n_slices) {
        if (is64) {
            st      = slices_raw[4 * t];       // low half of int64 start
            int e   = slices_raw[4 * t + 2];   // low half of int64 end
            len = e - st;
        } else {
            st      = slices_raw[2 * t];
            int e   = slices_raw[2 * t + 1];
            len = e - st;
        }
    }
    s_scan[t] = len;
    __syncthreads();

    // Hillis-Steele inclusive scan over MAX_SLICES entries.
    #pragma unroll
    for (int d = 1; d < MAX_SLICES; d <<= 1) {
        int v = (t >= d) ? s_scan[t - d] : 0;
        __syncthreads();
        s_scan[t] += v;
        __syncthreads();
    }

    if (t < n_slices) {
        int off = s_scan[t] - len;   // exclusive prefix
        for (int j = 0; j < len; j++)
            g_col_idx[off + j] = st + j;
    }
}

// Gather: out[r, p] = in[r, g_col_idx[p]]
// Grid: x tiles columns (256/block), y tiles rows (8/block).
__global__ void __launch_bounds__(TILE_COLS)
gather_kernel(const float* __restrict__ in, float* __restrict__ out, int out_cols) {
    int p = blockIdx.x * TILE_COLS + threadIdx.x;
    if (p >= out_cols) return;

    int idx = g_col_idx[p];
    int r0  = blockIdx.y * ROWS_PER_BLK;

    const float* src = in  + (size_t)r0 * IN_COLS  + idx;
    float*       dst = out + (size_t)r0 * out_cols + p;

    #pragma unroll
    for (int j = 0; j < ROWS_PER_BLK; j++) {
        dst[(size_t)j * out_cols] = __ldg(src + (size_t)j * IN_COLS);
    }
}

extern "C" void kernel_launch(void* const* d_in, const int* in_sizes, int n_in,
                              void* d_out, int out_size) {
    const float* input      = (const float*)d_in[0];
    const int*   slices_raw = (const int*)d_in[1];
    float*       out        = (float*)d_out;

    int n_slices = in_sizes[1] / 2;          // 600 (element count is 1200 for int32 or int64)
    int out_cols = out_size / N_ROWS;        // 12500

    build_col_idx_kernel<<<1, MAX_SLICES>>>(slices_raw, n_slices);

    dim3 grid((out_cols + TILE_COLS - 1) / TILE_COLS, N_ROWS / ROWS_PER_BLK);
    gather_kernel<<<grid, TILE_COLS>>>(input, out, out_cols);
}